// round 12
// baseline (speedup 1.0000x reference)
#include <cuda_runtime.h>
#include <cuda_bf16.h>
#include <math.h>

#define B_      8
#define H_      16
#define DIM_    2048
#define QLR_    1536
#define KVLR_   512
#define DN_     128
#define DR_     64
#define DV_     128
#define STARTP  8191
#define TTOT    8192
#define NSPLIT  36
#define CHUNK   228     // 36*228 = 8208 >= 8192
#define TTOK    8
#define EPS_    1e-6f
#define SCL2E_  0.10412468720927445f          // (128+64)^-0.5 * log2(e)

typedef unsigned long long ull;

// ---------------- scratch ----------------
__device__ __align__(16) float g_kvpe [B_*576];
__device__ __align__(16) float g_qraw [B_*QLR_];
__device__ __align__(16) float g_qa   [B_*QLR_];
__device__ __align__(16) float g_q    [B_*3072];
__device__ __align__(16) float g_qabs [B_*H_*KVLR_];
__device__ __align__(16) float g_qpe  [B_*H_*DR_];
__device__ __align__(16) float g_kvnew[B_*KVLR_];
__device__ __align__(16) float g_kpenew[B_*DR_];
__device__ __align__(16) float g_pout [(size_t)B_*NSPLIT*H_*KVLR_];
__device__ __align__(16) float g_pml  [B_*NSPLIT*H_*2];
__device__ __align__(16) float g_ctxv [B_*DIM_];

// ---------------- packed fp32x2 helpers ----------------
__device__ __forceinline__ void fma2(ull& d, ull a, ull b) {
    asm("fma.rn.f32x2 %0, %1, %2, %0;" : "+l"(d) : "l"(a), "l"(b));
}
__device__ __forceinline__ ull mul2(ull a, ull b) {
    ull r; asm("mul.rn.f32x2 %0, %1, %2;" : "=l"(r) : "l"(a), "l"(b)); return r;
}
__device__ __forceinline__ float2 u2f(ull v) {
    float2 r; asm("mov.b64 {%0,%1}, %2;" : "=f"(r.x), "=f"(r.y) : "l"(v)); return r;
}
__device__ __forceinline__ ull f2u(float a, float b) {
    ull r; asm("mov.b64 %0, {%1,%2};" : "=l"(r) : "f"(a), "f"(b)); return r;
}
__device__ __forceinline__ float ex2(float x) {
    float r; asm("ex2.approx.ftz.f32 %0, %1;" : "=f"(r) : "f"(x)); return r;
}

// ================= zero kernel: clear atomic targets =================
__global__ void zero_kernel(float* __restrict__ out) {
    int i = blockIdx.x * blockDim.x + threadIdx.x;
    if (i < B_ * QLR_)  g_qraw[i] = 0.f;
    if (i < B_ * 576)   g_kvpe[i] = 0.f;
    if (i < B_ * 3072)  g_q[i]    = 0.f;
    if (i < B_ * DIM_)  out[i]    = 0.f;
}

// ================= 8-batch GEMV core: W loads issued BEFORE X staging ============
__device__ __forceinline__ void gemv_core(const float* __restrict__ W,
                                          const float* __restrict__ bias,
                                          float* __restrict__ Y,
                                          const float* __restrict__ X,
                                          float* xs, int r, int C,
                                          int ystride, int halfsel,
                                          int tid, int lane) {
    int Ch = C >> 1;
    int Ch4 = Ch >> 2;
    const float4* Wr = (const float4*)(W + (size_t)r * C + (size_t)halfsel * Ch);
    int nk = Ch4 >> 5;

    float4 wv[8];
    #pragma unroll
    for (int k = 0; k < 8; k++) if (k < nk) wv[k] = Wr[lane + 32 * k];

    int c0 = halfsel * Ch;
    for (int i = tid; i < 8 * Ch4; i += 256) {
        int b = i / Ch4, j = i - b * Ch4;
        ((float4*)xs)[i] = *((const float4*)(X + (size_t)b * C + c0) + j);
    }
    __syncthreads();

    ull a0[B_], a1[B_];
    #pragma unroll
    for (int b = 0; b < B_; b++) { a0[b] = 0ull; a1[b] = 0ull; }

    const ulonglong2* xs2 = (const ulonglong2*)xs;
    #pragma unroll
    for (int k = 0; k < 8; k++) {
        if (k < nk) {
            ull w01 = f2u(wv[k].x, wv[k].y), w23 = f2u(wv[k].z, wv[k].w);
            int base = 32 * k + lane;
            #pragma unroll
            for (int b = 0; b < B_; b++) {
                ulonglong2 xv = xs2[b * Ch4 + base];
                fma2(a0[b], w01, xv.x);
                fma2(a1[b], w23, xv.y);
            }
        }
    }
    float bs = (halfsel == 0) ? bias[r] : 0.f;
    #pragma unroll
    for (int b = 0; b < B_; b++) {
        float2 p = u2f(a0[b]), q = u2f(a1[b]);
        float v = (p.x + p.y) + (q.x + q.y);
        #pragma unroll
        for (int off = 16; off; off >>= 1) v += __shfl_xor_sync(0xffffffffu, v, off);
        if (lane == 0) atomicAdd(&Y[(size_t)b * ystride + r], v + bs);
    }
}

__global__ void __launch_bounds__(256) gemv_kernel(const float* __restrict__ W,
                                                   const float* __restrict__ bias,
                                                   const float* __restrict__ X,
                                                   float* __restrict__ Y,
                                                   int R, int C, int ystride) {
    __shared__ __align__(16) float xs[8 * 1024];
    int tid = threadIdx.x, w = tid >> 5, lane = tid & 31;
    gemv_core(W, bias, Y, X, xs, blockIdx.x * 8 + w, C, ystride, blockIdx.y, tid, lane);
}

__global__ void __launch_bounds__(256) gemva_kernel(const float* __restrict__ wqa,
                                                    const float* __restrict__ wqab,
                                                    const float* __restrict__ wkva,
                                                    const float* __restrict__ wkvab,
                                                    const float* __restrict__ X) {
    __shared__ __align__(16) float xs[8 * 1024];
    int tid = threadIdx.x, w = tid >> 5, lane = tid & 31;
    int r = blockIdx.x * 8 + w;
    if (r < QLR_)
        gemv_core(wqa, wqab, g_qraw, X, xs, r, DIM_, QLR_, blockIdx.y, tid, lane);
    else
        gemv_core(wkva, wkvab, g_kvpe, X, xs, r - QLR_, DIM_, 576, blockIdx.y, tid, lane);
}

// ================= prep: rms(q_a) and rms(kv)+k_pe rope =================
__device__ __forceinline__ float block_sum(float v, float* red) {
    int w = threadIdx.x >> 5, lane = threadIdx.x & 31;
    #pragma unroll
    for (int off = 16; off; off >>= 1) v += __shfl_xor_sync(0xffffffffu, v, off);
    if (lane == 0) red[w] = v;
    __syncthreads();
    if (threadIdx.x < 32) {
        float t = (threadIdx.x < 8) ? red[threadIdx.x] : 0.f;
        #pragma unroll
        for (int off = 4; off; off >>= 1) t += __shfl_xor_sync(0xffffffffu, t, off);
        if (threadIdx.x == 0) red[0] = t;
    }
    __syncthreads();
    return red[0];
}

__global__ void __launch_bounds__(256) prep_kernel(const float* __restrict__ qnw,
                                                   const float* __restrict__ kvnw,
                                                   const float* __restrict__ fcos,
                                                   const float* __restrict__ fsin) {
    __shared__ float red[8];
    int tid = threadIdx.x;
    if (blockIdx.x < B_) {
        int b = blockIdx.x;
        const float* xr = g_qraw + b * QLR_;
        float ss = 0.f;
        for (int i = tid; i < QLR_; i += 256) { float v = xr[i]; ss += v * v; }
        float tot = block_sum(ss, red);
        float sc = rsqrtf(tot / QLR_ + EPS_);
        for (int i = tid; i < QLR_; i += 256) g_qa[b * QLR_ + i] = xr[i] * qnw[i] * sc;
    } else {
        int b = blockIdx.x - B_;
        const float* kvpe = g_kvpe + b * 576;
        float ss = 0.f;
        for (int i = tid; i < KVLR_; i += 256) { float v = kvpe[i]; ss += v * v; }
        float tot = block_sum(ss, red);
        float sc = rsqrtf(tot / KVLR_ + EPS_);
        for (int i = tid; i < KVLR_; i += 256) g_kvnew[b * KVLR_ + i] = kvpe[i] * kvnw[i] * sc;
        if (tid < 32) {
            int j = tid;
            float xr_ = kvpe[KVLR_ + 2 * j], xi = kvpe[KVLR_ + 2 * j + 1];
            float c = fcos[j], s = fsin[j];
            g_kpenew[b * DR_ + 2 * j]     = xr_ * c - xi * s;
            g_kpenew[b * DR_ + 2 * j + 1] = xr_ * s + xi * c;
        }
    }
}

// ================= qprep: q absorption + q_pe rope =================
__global__ void __launch_bounds__(256) qprep_kernel(const float* __restrict__ wkvb,
                                                    const float* __restrict__ fcos,
                                                    const float* __restrict__ fsin) {
    __shared__ float qn[2][DN_];
    int h = blockIdx.x, bp = blockIdx.y, tid = threadIdx.x;
    int b0 = bp * 2;
    #pragma unroll
    for (int u = 0; u < 2; u++) {
        const float* qsrc = g_q + (b0 + u) * 3072 + h * (DN_ + DR_);
        if (tid < DN_) qn[u][tid] = qsrc[tid];
        else if (tid < DN_ + 32) {
            int j = tid - DN_;
            float xr = qsrc[DN_ + 2 * j], xi = qsrc[DN_ + 2 * j + 1];
            float c = fcos[j], s = fsin[j];
            g_qpe[((b0 + u) * H_ + h) * DR_ + 2 * j]     = xr * c - xi * s;
            g_qpe[((b0 + u) * H_ + h) * DR_ + 2 * j + 1] = xr * s + xi * c;
        }
    }
    __syncthreads();
    const float* Wc = wkvb + (size_t)h * 256 * KVLR_;
    float acc00 = 0.f, acc01 = 0.f, acc10 = 0.f, acc11 = 0.f;
    #pragma unroll 4
    for (int d = 0; d < DN_; d++) {
        float w0 = Wc[(size_t)d * KVLR_ + tid];
        float w1 = Wc[(size_t)d * KVLR_ + tid + 256];
        float q0 = qn[0][d], q1 = qn[1][d];
        acc00 = fmaf(q0, w0, acc00); acc01 = fmaf(q0, w1, acc01);
        acc10 = fmaf(q1, w0, acc10); acc11 = fmaf(q1, w1, acc11);
    }
    g_qabs[(size_t)(b0 * H_ + h) * KVLR_ + tid]             = acc00;
    g_qabs[(size_t)(b0 * H_ + h) * KVLR_ + tid + 256]       = acc01;
    g_qabs[(size_t)((b0 + 1) * H_ + h) * KVLR_ + tid]       = acc10;
    g_qabs[(size_t)((b0 + 1) * H_ + h) * KVLR_ + tid + 256] = acc11;
}

// ================= flash-decode attention: 16-slice + kr caching + 16 warps/SM ========
// 256 thr / 8 warps; warp = 2 heads; lane = hl*16 + s (hl=lane>>4, s=lane&15).
// Lane owns row-f4 indices {s+16i, i=0..8}: i=0..7 = kv (0..127), i=8 = pe (128..143).
// Per token: 9 independent LDS.128 into kr[], QK from regs (4 chains, depth 9->5),
// 4-stage 16-lane shuffle reduce, lazy rescale, PV from the SAME regs.
// Live regs: q 36 + kr 36 + acc 32 + misc ~20 ≈ 124 < 128 (2 CTA/SM cap).
__global__ void __launch_bounds__(256, 2) attn_kernel(const float* __restrict__ kvpre,
                                                      const float* __restrict__ pepre) {
    __shared__ __align__(16) float4 tile[2][TTOK][144];
    int b = blockIdx.y, split = blockIdx.x;
    int t0 = split * CHUNK;
    int t1 = min(t0 + CHUNK, TTOT);
    int tid = threadIdx.x, w = tid >> 5, lane = tid & 31;
    int hl = lane >> 4, s = lane & 15;
    int head = w * 2 + hl;

    ulonglong2 q[9];
    {
        const ulonglong2* qa = (const ulonglong2*)(g_qabs + (size_t)(b * H_ + head) * KVLR_);
        #pragma unroll
        for (int i = 0; i < 8; i++) q[i] = qa[s + 16 * i];
        const ulonglong2* qp = (const ulonglong2*)(g_qpe + (size_t)(b * H_ + head) * DR_);
        q[8] = qp[s];
    }
    ull acc[16];
    #pragma unroll
    for (int i = 0; i < 16; i++) acc[i] = 0ull;
    float m = -INFINITY, l = 0.f;

    const float4* kv4  = (const float4*)kvpre;
    const float4* pe4  = (const float4*)pepre;
    const float4* kvn4 = (const float4*)g_kvnew;
    const float4* pen4 = (const float4*)g_kpenew;

    int ntiles = (t1 - t0 + TTOK - 1) / TTOK;

    auto issue_tile = [&](int buf, int ti) {
        int tb = t0 + ti * TTOK;
        int cnt = min(TTOK, t1 - tb);
        for (int idx = tid; idx < cnt * 144; idx += 256) {
            int tk = idx / 144, j = idx - tk * 144;
            int t = tb + tk;
            const float4* src;
            if (j < 128)
                src = (t < STARTP) ? (kv4 + ((size_t)b * STARTP + t) * 128 + j)
                                   : (kvn4 + b * 128 + j);
            else
                src = (t < STARTP) ? (pe4 + ((size_t)b * STARTP + t) * 16 + (j - 128))
                                   : (pen4 + b * 16 + (j - 128));
            unsigned sa = (unsigned)__cvta_generic_to_shared(&tile[buf][tk][j]);
            asm volatile("cp.async.cg.shared.global [%0], [%1], 16;\n" :: "r"(sa), "l"(src));
        }
        asm volatile("cp.async.commit_group;\n");
    };

    issue_tile(0, 0);
    for (int ti = 0; ti < ntiles; ti++) {
        if (ti + 1 < ntiles) {
            issue_tile((ti + 1) & 1, ti + 1);
            asm volatile("cp.async.wait_group 1;\n");
        } else {
            asm volatile("cp.async.wait_group 0;\n");
        }
        __syncthreads();
        int tb = t0 + ti * TTOK;
        int cnt = min(TTOK, t1 - tb);
        const float4 (*tl)[144] = tile[ti & 1];
        for (int tk = 0; tk < cnt; tk++) {
            const ulonglong2* row = (const ulonglong2*)tl[tk];
            // ---- load row ONCE into registers (9 independent LDS.128) ----
            ulonglong2 kr[9];
            #pragma unroll
            for (int i = 0; i < 9; i++) kr[i] = row[s + 16 * i];
            // ---- QK from registers: 4 chains, dep depth 5 ----
            ull a0 = 0ull, a1 = 0ull, a2 = 0ull, a3 = 0ull;
            #pragma unroll
            for (int i = 0; i < 4; i++) {
                fma2(a0, q[i].x, kr[i].x);
                fma2(a1, q[i].y, kr[i].y);
                fma2(a2, q[i + 4].x, kr[i + 4].x);
                fma2(a3, q[i + 4].y, kr[i + 4].y);
            }
            fma2(a0, q[8].x, kr[8].x);
            fma2(a1, q[8].y, kr[8].y);
            float2 f0 = u2f(a0), f1 = u2f(a1), f2 = u2f(a2), f3 = u2f(a3);
            float sc = ((f0.x + f0.y) + (f1.x + f1.y)) + ((f2.x + f2.y) + (f3.x + f3.y));
            sc += __shfl_xor_sync(0xffffffffu, sc, 1);
            sc += __shfl_xor_sync(0xffffffffu, sc, 2);
            sc += __shfl_xor_sync(0xffffffffu, sc, 4);
            sc += __shfl_xor_sync(0xffffffffu, sc, 8);
            sc *= SCL2E_;
            if (sc > m) {                       // lazy rescale (rare)
                float corr = ex2(m - sc);
                m = sc;
                l *= corr;
                ull c2 = f2u(corr, corr);
                #pragma unroll
                for (int i = 0; i < 16; i++) acc[i] = mul2(acc[i], c2);
            }
            float p = ex2(sc - m);
            l += p;
            ull p2 = f2u(p, p);
            // ---- PV from the SAME registers (kv part: kr[0..7]) ----
            #pragma unroll
            for (int i = 0; i < 8; i++) {
                fma2(acc[2 * i],     p2, kr[i].x);
                fma2(acc[2 * i + 1], p2, kr[i].y);
            }
        }
        __syncthreads();
    }
    float4* dst = (float4*)(g_pout + ((size_t)(b * NSPLIT + split) * H_ + head) * KVLR_);
    #pragma unroll
    for (int i = 0; i < 8; i++) {
        float2 lo = u2f(acc[2 * i]), hi = u2f(acc[2 * i + 1]);
        dst[s + 16 * i] = make_float4(lo.x, lo.y, hi.x, hi.y);
    }
    if (s == 0) {
        float* ml = g_pml + ((b * NSPLIT + split) * H_ + head) * 2;
        ml[0] = m;     // log2 domain
        ml[1] = l;
    }
}

// ================= postcomb: split-combine + W_uv projection, per (b,h) =================
__global__ void __launch_bounds__(256) postcomb_kernel(const float* __restrict__ wkvb) {
    __shared__ float msm[NSPLIT], lsm[NSPLIT], esm[NSPLIT];
    __shared__ float invL;
    __shared__ __align__(16) float cs[KVLR_];
    int h = blockIdx.x, b = blockIdx.y, tid = threadIdx.x;
    int w = tid >> 5, lane = tid & 31;

    if (tid < NSPLIT) {
        const float* ml = g_pml + ((b * NSPLIT + tid) * H_ + h) * 2;
        msm[tid] = ml[0];
        lsm[tid] = ml[1];
    }
    __syncthreads();
    if (tid == 0) {
        float M = -INFINITY;
        for (int sp = 0; sp < NSPLIT; sp++) M = fmaxf(M, msm[sp]);
        float L = 0.f;
        for (int sp = 0; sp < NSPLIT; sp++) {
            float e = ex2(msm[sp] - M);
            esm[sp] = e;
            L += e * lsm[sp];
        }
        invL = 1.0f / L;
    }
    __syncthreads();
    float a0 = 0.f, a1 = 0.f;
    #pragma unroll 4
    for (int sp = 0; sp < NSPLIT; sp++) {
        float e = esm[sp];
        const float* pp = g_pout + ((size_t)(b * NSPLIT + sp) * H_ + h) * KVLR_;
        a0 += e * pp[tid];
        a1 += e * pp[tid + 256];
    }
    float iv = invL;
    cs[tid]       = a0 * iv;
    cs[tid + 256] = a1 * iv;
    __syncthreads();

    const ulonglong2* cs2 = (const ulonglong2*)cs;
    #pragma unroll
    for (int k = 0; k < 16; k++) {
        int d = w * 16 + k;
        const ulonglong2* wr = (const ulonglong2*)(wkvb + (size_t)(h * 256 + DN_ + d) * KVLR_);
        ull a0u = 0ull, a1u = 0ull;
        #pragma unroll
        for (int j = lane; j < 128; j += 32) {
            ulonglong2 wv = __ldg(wr + j);
            ulonglong2 xv = cs2[j];
            fma2(a0u, wv.x, xv.x);
            fma2(a1u, wv.y, xv.y);
        }
        float2 f0 = u2f(a0u), f1 = u2f(a1u);
        float a = (f0.x + f0.y) + (f1.x + f1.y);
        #pragma unroll
        for (int off = 16; off; off >>= 1) a += __shfl_xor_sync(0xffffffffu, a, off);
        if (lane == 0) g_ctxv[b * DIM_ + h * DV_ + d] = a;
    }
}

// ---------------- launch ----------------
extern "C" void kernel_launch(void* const* d_in, const int* in_sizes, int n_in,
                              void* d_out, int out_size) {
    const float* x     = (const float*)d_in[0];
    const float* fcos  = (const float*)d_in[2];
    const float* fsin  = (const float*)d_in[3];
    const float* kvpre = (const float*)d_in[4];
    const float* pepre = (const float*)d_in[5];
    const float* wqa   = (const float*)d_in[6];
    const float* wqab  = (const float*)d_in[7];
    const float* qnw   = (const float*)d_in[8];
    const float* wqb   = (const float*)d_in[9];
    const float* wqbb  = (const float*)d_in[10];
    const float* wkva  = (const float*)d_in[11];
    const float* wkvab = (const float*)d_in[12];
    const float* kvnw  = (const float*)d_in[13];
    const float* wkvb  = (const float*)d_in[14];
    const float* wo    = (const float*)d_in[15];
    const float* wob   = (const float*)d_in[16];
    float* out = (float*)d_out;

    float* g_qa_p;    cudaGetSymbolAddress((void**)&g_qa_p,    g_qa);
    float* g_q_p;     cudaGetSymbolAddress((void**)&g_q_p,     g_q);
    float* g_ctxv_p;  cudaGetSymbolAddress((void**)&g_ctxv_p,  g_ctxv);

    zero_kernel<<<(B_ * 3072 + 255) / 256, 256>>>(out);
    gemva_kernel<<<dim3((QLR_ + 576) / 8, 2), 256>>>(wqa, wqab, wkva, wkvab, x);
    prep_kernel<<<16, 256>>>(qnw, kvnw, fcos, fsin);
    gemv_kernel<<<dim3(3072 / 8, 2), 256>>>(wqb, wqbb, g_qa_p, g_q_p, 3072, QLR_, 3072);
    qprep_kernel<<<dim3(H_, 4), 256>>>(wkvb, fcos, fsin);
    attn_kernel<<<dim3(NSPLIT, B_), 256>>>(kvpre, pepre);
    postcomb_kernel<<<dim3(H_, B_), 256>>>(wkvb);
    gemv_kernel<<<dim3(DIM_ / 8, 2), 256>>>(wo, wob, g_ctxv_p, out, DIM_, DIM_, DIM_);
}

// round 13
// speedup vs baseline: 1.4362x; 1.4362x over previous
#include <cuda_runtime.h>
#include <cuda_bf16.h>
#include <math.h>

#define B_      8
#define H_      16
#define DIM_    2048
#define QLR_    1536
#define KVLR_   512
#define DN_     128
#define DR_     64
#define DV_     128
#define STARTP  8191
#define TTOT    8192
#define NSPLIT  36
#define CHUNK   228     // 36*228 = 8208 >= 8192
#define TTOK    8
#define EPS_    1e-6f
#define SCL2E_  0.10412468720927445f          // (128+64)^-0.5 * log2(e)

typedef unsigned long long ull;

// ---------------- scratch ----------------
__device__ __align__(16) float g_kvpe [B_*576];
__device__ __align__(16) float g_kvpe2[B_*576];
__device__ __align__(16) float g_qraw [B_*QLR_];
__device__ __align__(16) float g_qraw2[B_*QLR_];
__device__ __align__(16) float g_qa   [B_*QLR_];
__device__ __align__(16) float g_q    [B_*3072];
__device__ __align__(16) float g_q2   [B_*3072];
__device__ __align__(16) float g_qabs [B_*H_*KVLR_];
__device__ __align__(16) float g_qpe  [B_*H_*DR_];
__device__ __align__(16) float g_kvnew[B_*KVLR_];
__device__ __align__(16) float g_kpenew[B_*DR_];
__device__ __align__(16) float g_pout [(size_t)B_*NSPLIT*H_*KVLR_];
__device__ __align__(16) float g_pml  [B_*NSPLIT*H_*2];
__device__ __align__(16) float g_ctxv [B_*DIM_];

// ---------------- packed fp32x2 helpers ----------------
__device__ __forceinline__ void fma2(ull& d, ull a, ull b) {
    asm("fma.rn.f32x2 %0, %1, %2, %0;" : "+l"(d) : "l"(a), "l"(b));
}
__device__ __forceinline__ ull mul2(ull a, ull b) {
    ull r; asm("mul.rn.f32x2 %0, %1, %2;" : "=l"(r) : "l"(a), "l"(b)); return r;
}
__device__ __forceinline__ float2 u2f(ull v) {
    float2 r; asm("mov.b64 {%0,%1}, %2;" : "=f"(r.x), "=f"(r.y) : "l"(v)); return r;
}
__device__ __forceinline__ ull f2u(float a, float b) {
    ull r; asm("mov.b64 %0, {%1,%2};" : "=l"(r) : "f"(a), "f"(b)); return r;
}
__device__ __forceinline__ float ex2(float x) {
    float r; asm("ex2.approx.ftz.f32 %0, %1;" : "=f"(r) : "f"(x)); return r;
}

// ================= 8-batch GEMV core: halves write partials (no zero needed) ============
// use_atomic=true keeps atomicAdd (caller must pre-zero Y); else plain store to the
// half-specific buffer.
__device__ __forceinline__ void gemv_core(const float* __restrict__ W,
                                          const float* __restrict__ bias,
                                          float* __restrict__ Y,
                                          const float* __restrict__ X,
                                          float* xs, int r, int C,
                                          int ystride, int halfsel, bool use_atomic,
                                          int tid, int lane) {
    int Ch = C >> 1;
    int Ch4 = Ch >> 2;
    const float4* Wr = (const float4*)(W + (size_t)r * C + (size_t)halfsel * Ch);
    int nk = Ch4 >> 5;

    float4 wv[8];
    #pragma unroll
    for (int k = 0; k < 8; k++) if (k < nk) wv[k] = Wr[lane + 32 * k];

    int c0 = halfsel * Ch;
    for (int i = tid; i < 8 * Ch4; i += 256) {
        int b = i / Ch4, j = i - b * Ch4;
        ((float4*)xs)[i] = *((const float4*)(X + (size_t)b * C + c0) + j);
    }
    __syncthreads();

    ull a0[B_], a1[B_];
    #pragma unroll
    for (int b = 0; b < B_; b++) { a0[b] = 0ull; a1[b] = 0ull; }

    const ulonglong2* xs2 = (const ulonglong2*)xs;
    #pragma unroll
    for (int k = 0; k < 8; k++) {
        if (k < nk) {
            ull w01 = f2u(wv[k].x, wv[k].y), w23 = f2u(wv[k].z, wv[k].w);
            int base = 32 * k + lane;
            #pragma unroll
            for (int b = 0; b < B_; b++) {
                ulonglong2 xv = xs2[b * Ch4 + base];
                fma2(a0[b], w01, xv.x);
                fma2(a1[b], w23, xv.y);
            }
        }
    }
    float bs = (halfsel == 0) ? bias[r] : 0.f;
    #pragma unroll
    for (int b = 0; b < B_; b++) {
        float2 p = u2f(a0[b]), q = u2f(a1[b]);
        float v = (p.x + p.y) + (q.x + q.y);
        #pragma unroll
        for (int off = 16; off; off >>= 1) v += __shfl_xor_sync(0xffffffffu, v, off);
        if (lane == 0) {
            if (use_atomic) atomicAdd(&Y[(size_t)b * ystride + r], v + bs);
            else            Y[(size_t)b * ystride + r] = v + bs;
        }
    }
}

// wqb gemv: halves -> g_q / g_q2
__global__ void __launch_bounds__(256) gemvqb_kernel(const float* __restrict__ W,
                                                     const float* __restrict__ bias,
                                                     const float* __restrict__ X_unused) {
    __shared__ __align__(16) float xs[8 * 1024];
    int tid = threadIdx.x, w = tid >> 5, lane = tid & 31;
    float* Y = blockIdx.y ? g_q2 : g_q;
    gemv_core(W, bias, Y, g_qa, xs, blockIdx.x * 8 + w, QLR_, 3072, blockIdx.y, false, tid, lane);
}

// wo gemv: atomic into pre-zeroed out
__global__ void __launch_bounds__(256) gemvwo_kernel(const float* __restrict__ W,
                                                     const float* __restrict__ bias,
                                                     float* __restrict__ out) {
    __shared__ __align__(16) float xs[8 * 1024];
    int tid = threadIdx.x, w = tid >> 5, lane = tid & 31;
    gemv_core(W, bias, out, g_ctxv, xs, blockIdx.x * 8 + w, DIM_, DIM_, blockIdx.y, true, tid, lane);
}

// fused wq_a + wkv_a: halves -> (g_qraw|g_qraw2) / (g_kvpe|g_kvpe2)
__global__ void __launch_bounds__(256) gemva_kernel(const float* __restrict__ wqa,
                                                    const float* __restrict__ wqab,
                                                    const float* __restrict__ wkva,
                                                    const float* __restrict__ wkvab,
                                                    const float* __restrict__ X) {
    __shared__ __align__(16) float xs[8 * 1024];
    int tid = threadIdx.x, w = tid >> 5, lane = tid & 31;
    int r = blockIdx.x * 8 + w;
    if (r < QLR_) {
        float* Y = blockIdx.y ? g_qraw2 : g_qraw;
        gemv_core(wqa, wqab, Y, X, xs, r, DIM_, QLR_, blockIdx.y, false, tid, lane);
    } else {
        float* Y = blockIdx.y ? g_kvpe2 : g_kvpe;
        gemv_core(wkva, wkvab, Y, X, xs, r - QLR_, DIM_, 576, blockIdx.y, false, tid, lane);
    }
}

// ================= prep: rms(q_a) and rms(kv)+k_pe rope (reads half-sums) =================
__device__ __forceinline__ float block_sum(float v, float* red) {
    int w = threadIdx.x >> 5, lane = threadIdx.x & 31;
    #pragma unroll
    for (int off = 16; off; off >>= 1) v += __shfl_xor_sync(0xffffffffu, v, off);
    if (lane == 0) red[w] = v;
    __syncthreads();
    if (threadIdx.x < 32) {
        float t = (threadIdx.x < 8) ? red[threadIdx.x] : 0.f;
        #pragma unroll
        for (int off = 4; off; off >>= 1) t += __shfl_xor_sync(0xffffffffu, t, off);
        if (threadIdx.x == 0) red[0] = t;
    }
    __syncthreads();
    return red[0];
}

__global__ void __launch_bounds__(256) prep_kernel(const float* __restrict__ qnw,
                                                   const float* __restrict__ kvnw,
                                                   const float* __restrict__ fcos,
                                                   const float* __restrict__ fsin) {
    __shared__ float red[8];
    int tid = threadIdx.x;
    if (blockIdx.x < B_) {
        int b = blockIdx.x;
        const float* x0 = g_qraw + b * QLR_;
        const float* x1 = g_qraw2 + b * QLR_;
        float ss = 0.f;
        for (int i = tid; i < QLR_; i += 256) { float v = x0[i] + x1[i]; ss += v * v; }
        float tot = block_sum(ss, red);
        float sc = rsqrtf(tot / QLR_ + EPS_);
        for (int i = tid; i < QLR_; i += 256)
            g_qa[b * QLR_ + i] = (x0[i] + x1[i]) * qnw[i] * sc;
    } else {
        int b = blockIdx.x - B_;
        const float* k0 = g_kvpe + b * 576;
        const float* k1 = g_kvpe2 + b * 576;
        float ss = 0.f;
        for (int i = tid; i < KVLR_; i += 256) { float v = k0[i] + k1[i]; ss += v * v; }
        float tot = block_sum(ss, red);
        float sc = rsqrtf(tot / KVLR_ + EPS_);
        for (int i = tid; i < KVLR_; i += 256)
            g_kvnew[b * KVLR_ + i] = (k0[i] + k1[i]) * kvnw[i] * sc;
        if (tid < 32) {
            int j = tid;
            float xr_ = k0[KVLR_ + 2 * j] + k1[KVLR_ + 2 * j];
            float xi  = k0[KVLR_ + 2 * j + 1] + k1[KVLR_ + 2 * j + 1];
            float c = fcos[j], s = fsin[j];
            g_kpenew[b * DR_ + 2 * j]     = xr_ * c - xi * s;
            g_kpenew[b * DR_ + 2 * j + 1] = xr_ * s + xi * c;
        }
    }
}

// ================= qprep: q absorption + q_pe rope (reads half-sums) =================
__global__ void __launch_bounds__(256) qprep_kernel(const float* __restrict__ wkvb,
                                                    const float* __restrict__ fcos,
                                                    const float* __restrict__ fsin) {
    __shared__ float qn[2][DN_];
    int h = blockIdx.x, bp = blockIdx.y, tid = threadIdx.x;
    int b0 = bp * 2;
    #pragma unroll
    for (int u = 0; u < 2; u++) {
        const float* q0 = g_q  + (b0 + u) * 3072 + h * (DN_ + DR_);
        const float* q1 = g_q2 + (b0 + u) * 3072 + h * (DN_ + DR_);
        if (tid < DN_) qn[u][tid] = q0[tid] + q1[tid];
        else if (tid < DN_ + 32) {
            int j = tid - DN_;
            float xr = q0[DN_ + 2 * j] + q1[DN_ + 2 * j];
            float xi = q0[DN_ + 2 * j + 1] + q1[DN_ + 2 * j + 1];
            float c = fcos[j], s = fsin[j];
            g_qpe[((b0 + u) * H_ + h) * DR_ + 2 * j]     = xr * c - xi * s;
            g_qpe[((b0 + u) * H_ + h) * DR_ + 2 * j + 1] = xr * s + xi * c;
        }
    }
    __syncthreads();
    const float* Wc = wkvb + (size_t)h * 256 * KVLR_;
    float acc00 = 0.f, acc01 = 0.f, acc10 = 0.f, acc11 = 0.f;
    #pragma unroll 4
    for (int d = 0; d < DN_; d++) {
        float w0 = Wc[(size_t)d * KVLR_ + tid];
        float w1 = Wc[(size_t)d * KVLR_ + tid + 256];
        float q0 = qn[0][d], q1 = qn[1][d];
        acc00 = fmaf(q0, w0, acc00); acc01 = fmaf(q0, w1, acc01);
        acc10 = fmaf(q1, w0, acc10); acc11 = fmaf(q1, w1, acc11);
    }
    g_qabs[(size_t)(b0 * H_ + h) * KVLR_ + tid]             = acc00;
    g_qabs[(size_t)(b0 * H_ + h) * KVLR_ + tid + 256]       = acc01;
    g_qabs[(size_t)((b0 + 1) * H_ + h) * KVLR_ + tid]       = acc10;
    g_qabs[(size_t)((b0 + 1) * H_ + h) * KVLR_ + tid + 256] = acc11;
}

// ================= flash-decode attention: R11 winner + 4-chain QK ========
// 128 thr / 4 warps; warp = 4 heads; lane = hl*8+s (8-slice, broadcast-optimal).
// Per token: 18 independent LDS.128 into kr[], QK from regs (4 chains, depth 9),
// softmax, PV from the SAME regs. Live regs ~235 < 256 (occ-2 cap).
__global__ void __launch_bounds__(128, 2) attn_kernel(const float* __restrict__ kvpre,
                                                      const float* __restrict__ pepre) {
    __shared__ __align__(16) float4 tile[2][TTOK][144];
    int b = blockIdx.y, split = blockIdx.x;
    int t0 = split * CHUNK;
    int t1 = min(t0 + CHUNK, TTOT);
    int tid = threadIdx.x, w = tid >> 5, lane = tid & 31;
    int hl = lane >> 3, s = lane & 7;
    int head = w * 4 + hl;

    ulonglong2 q[18];
    {
        const ulonglong2* qa = (const ulonglong2*)(g_qabs + (size_t)(b * H_ + head) * KVLR_);
        #pragma unroll
        for (int i = 0; i < 16; i++) q[i] = qa[s + 8 * i];
        const ulonglong2* qp = (const ulonglong2*)(g_qpe + (size_t)(b * H_ + head) * DR_);
        q[16] = qp[s];
        q[17] = qp[s + 8];
    }
    ull acc[32];
    #pragma unroll
    for (int i = 0; i < 32; i++) acc[i] = 0ull;
    float m = -INFINITY, l = 0.f;

    const float4* kv4  = (const float4*)kvpre;
    const float4* pe4  = (const float4*)pepre;
    const float4* kvn4 = (const float4*)g_kvnew;
    const float4* pen4 = (const float4*)g_kpenew;

    int ntiles = (t1 - t0 + TTOK - 1) / TTOK;

    auto issue_tile = [&](int buf, int ti) {
        int tb = t0 + ti * TTOK;
        int cnt = min(TTOK, t1 - tb);
        for (int idx = tid; idx < cnt * 144; idx += 128) {
            int tk = idx / 144, j = idx - tk * 144;
            int t = tb + tk;
            const float4* src;
            if (j < 128)
                src = (t < STARTP) ? (kv4 + ((size_t)b * STARTP + t) * 128 + j)
                                   : (kvn4 + b * 128 + j);
            else
                src = (t < STARTP) ? (pe4 + ((size_t)b * STARTP + t) * 16 + (j - 128))
                                   : (pen4 + b * 16 + (j - 128));
            unsigned sa = (unsigned)__cvta_generic_to_shared(&tile[buf][tk][j]);
            asm volatile("cp.async.cg.shared.global [%0], [%1], 16;\n" :: "r"(sa), "l"(src));
        }
        asm volatile("cp.async.commit_group;\n");
    };

    issue_tile(0, 0);
    for (int ti = 0; ti < ntiles; ti++) {
        if (ti + 1 < ntiles) {
            issue_tile((ti + 1) & 1, ti + 1);
            asm volatile("cp.async.wait_group 1;\n");
        } else {
            asm volatile("cp.async.wait_group 0;\n");
        }
        __syncthreads();
        int tb = t0 + ti * TTOK;
        int cnt = min(TTOK, t1 - tb);
        const float4 (*tl)[144] = tile[ti & 1];
        for (int tk = 0; tk < cnt; tk++) {
            const ulonglong2* row = (const ulonglong2*)tl[tk];
            // ---- load row ONCE into registers (18 independent LDS.128) ----
            ulonglong2 kr[18];
            #pragma unroll
            for (int i = 0; i < 16; i++) kr[i] = row[s + 8 * i];
            kr[16] = row[128 + s];
            kr[17] = row[128 + s + 8];
            // ---- QK from registers: 4 chains, dep depth 9 ----
            ull a0 = 0ull, a1 = 0ull, a2 = 0ull, a3 = 0ull;
            #pragma unroll
            for (int i = 0; i < 9; i++) {
                fma2(a0, q[i].x, kr[i].x);
                fma2(a1, q[i].y, kr[i].y);
                fma2(a2, q[i + 9].x, kr[i + 9].x);
                fma2(a3, q[i + 9].y, kr[i + 9].y);
            }
            float2 f0 = u2f(a0), f1 = u2f(a1), f2 = u2f(a2), f3 = u2f(a3);
            float sc = ((f0.x + f0.y) + (f1.x + f1.y)) + ((f2.x + f2.y) + (f3.x + f3.y));
            sc += __shfl_xor_sync(0xffffffffu, sc, 1);
            sc += __shfl_xor_sync(0xffffffffu, sc, 2);
            sc += __shfl_xor_sync(0xffffffffu, sc, 4);
            sc *= SCL2E_;
            if (sc > m) {                       // lazy rescale (rare)
                float corr = ex2(m - sc);
                m = sc;
                l *= corr;
                ull c2 = f2u(corr, corr);
                #pragma unroll
                for (int i = 0; i < 32; i++) acc[i] = mul2(acc[i], c2);
            }
            float p = ex2(sc - m);
            l += p;
            ull p2 = f2u(p, p);
            // ---- PV from the SAME registers (no smem re-read) ----
            #pragma unroll
            for (int i = 0; i < 16; i++) {
                fma2(acc[2 * i],     p2, kr[i].x);
                fma2(acc[2 * i + 1], p2, kr[i].y);
            }
        }
        __syncthreads();
    }
    float4* dst = (float4*)(g_pout + ((size_t)(b * NSPLIT + split) * H_ + head) * KVLR_);
    #pragma unroll
    for (int i = 0; i < 16; i++) {
        float2 lo = u2f(acc[2 * i]), hi = u2f(acc[2 * i + 1]);
        dst[s + 8 * i] = make_float4(lo.x, lo.y, hi.x, hi.y);
    }
    if (s == 0) {
        float* ml = g_pml + ((b * NSPLIT + split) * H_ + head) * 2;
        ml[0] = m;     // log2 domain
        ml[1] = l;
    }
}

// ================= postcomb: combine + W_uv projection + zero out slice =================
__global__ void __launch_bounds__(256) postcomb_kernel(const float* __restrict__ wkvb,
                                                       float* __restrict__ out) {
    __shared__ float msm[NSPLIT], lsm[NSPLIT], esm[NSPLIT];
    __shared__ float invL;
    __shared__ __align__(16) float cs[KVLR_];
    int h = blockIdx.x, b = blockIdx.y, tid = threadIdx.x;
    int w = tid >> 5, lane = tid & 31;

    // zero this block's slice of out (consumed by the atomic wo gemv next)
    if (tid < DV_) out[b * DIM_ + h * DV_ + tid] = 0.f;

    if (tid < NSPLIT) {
        const float* ml = g_pml + ((b * NSPLIT + tid) * H_ + h) * 2;
        msm[tid] = ml[0];
        lsm[tid] = ml[1];
    }
    __syncthreads();
    if (tid == 0) {
        float M = -INFINITY;
        for (int sp = 0; sp < NSPLIT; sp++) M = fmaxf(M, msm[sp]);
        float L = 0.f;
        for (int sp = 0; sp < NSPLIT; sp++) {
            float e = ex2(msm[sp] - M);
            esm[sp] = e;
            L += e * lsm[sp];
        }
        invL = 1.0f / L;
    }
    __syncthreads();
    float a0 = 0.f, a1 = 0.f;
    #pragma unroll 4
    for (int sp = 0; sp < NSPLIT; sp++) {
        float e = esm[sp];
        const float* pp = g_pout + ((size_t)(b * NSPLIT + sp) * H_ + h) * KVLR_;
        a0 += e * pp[tid];
        a1 += e * pp[tid + 256];
    }
    float iv = invL;
    cs[tid]       = a0 * iv;
    cs[tid + 256] = a1 * iv;
    __syncthreads();

    const ulonglong2* cs2 = (const ulonglong2*)cs;
    #pragma unroll
    for (int k = 0; k < 16; k++) {
        int d = w * 16 + k;
        const ulonglong2* wr = (const ulonglong2*)(wkvb + (size_t)(h * 256 + DN_ + d) * KVLR_);
        ull a0u = 0ull, a1u = 0ull;
        #pragma unroll
        for (int j = lane; j < 128; j += 32) {
            ulonglong2 wv = __ldg(wr + j);
            ulonglong2 xv = cs2[j];
            fma2(a0u, wv.x, xv.x);
            fma2(a1u, wv.y, xv.y);
        }
        float2 f0 = u2f(a0u), f1 = u2f(a1u);
        float a = (f0.x + f0.y) + (f1.x + f1.y);
        #pragma unroll
        for (int off = 16; off; off >>= 1) a += __shfl_xor_sync(0xffffffffu, a, off);
        if (lane == 0) g_ctxv[b * DIM_ + h * DV_ + d] = a;
    }
}

// ---------------- launch ----------------
extern "C" void kernel_launch(void* const* d_in, const int* in_sizes, int n_in,
                              void* d_out, int out_size) {
    const float* x     = (const float*)d_in[0];
    const float* fcos  = (const float*)d_in[2];
    const float* fsin  = (const float*)d_in[3];
    const float* kvpre = (const float*)d_in[4];
    const float* pepre = (const float*)d_in[5];
    const float* wqa   = (const float*)d_in[6];
    const float* wqab  = (const float*)d_in[7];
    const float* qnw   = (const float*)d_in[8];
    const float* wqb   = (const float*)d_in[9];
    const float* wqbb  = (const float*)d_in[10];
    const float* wkva  = (const float*)d_in[11];
    const float* wkvab = (const float*)d_in[12];
    const float* kvnw  = (const float*)d_in[13];
    const float* wkvb  = (const float*)d_in[14];
    const float* wo    = (const float*)d_in[15];
    const float* wob   = (const float*)d_in[16];
    float* out = (float*)d_out;

    gemva_kernel<<<dim3((QLR_ + 576) / 8, 2), 256>>>(wqa, wqab, wkva, wkvab, x);
    prep_kernel<<<16, 256>>>(qnw, kvnw, fcos, fsin);
    gemvqb_kernel<<<dim3(3072 / 8, 2), 256>>>(wqb, wqbb, nullptr);
    qprep_kernel<<<dim3(H_, 4), 256>>>(wkvb, fcos, fsin);
    attn_kernel<<<dim3(NSPLIT, B_), 128>>>(kvpre, pepre);
    postcomb_kernel<<<dim3(H_, B_), 256>>>(wkvb, out);
    gemvwo_kernel<<<dim3(DIM_ / 8, 2), 256>>>(wo, wob, out);
}

// round 14
// speedup vs baseline: 1.5317x; 1.0665x over previous
#include <cuda_runtime.h>
#include <cuda_bf16.h>
#include <math.h>

#define B_      8
#define H_      16
#define DIM_    2048
#define QLR_    1536
#define KVLR_   512
#define DN_     128
#define DR_     64
#define DV_     128
#define STARTP  8191
#define TTOT    8192
#define NSPLIT  36
#define CHUNK   228     // 36*228 = 8208 >= 8192
#define TTOK    8
#define EPS_    1e-6f
#define SCL2E_  0.10412468720927445f          // (128+64)^-0.5 * log2(e)

typedef unsigned long long ull;

// ---------------- scratch ----------------
__device__ __align__(16) float g_kvpe [B_*576];
__device__ __align__(16) float g_kvpe2[B_*576];
__device__ __align__(16) float g_qraw [B_*QLR_];
__device__ __align__(16) float g_qraw2[B_*QLR_];
__device__ __align__(16) float g_qa   [B_*QLR_];
__device__ __align__(16) float g_q    [B_*3072];
__device__ __align__(16) float g_q2   [B_*3072];
__device__ __align__(16) float g_qabs [B_*H_*KVLR_];
__device__ __align__(16) float g_qpe  [B_*H_*DR_];
__device__ __align__(16) float g_kvnew[B_*KVLR_];
__device__ __align__(16) float g_kpenew[B_*DR_];
__device__ __align__(16) float g_pout [(size_t)B_*NSPLIT*H_*KVLR_];
__device__ __align__(16) float g_pml  [B_*NSPLIT*H_*2];
__device__ __align__(16) float g_ctxv [B_*DIM_];

// ---------------- packed fp32x2 helpers ----------------
__device__ __forceinline__ void fma2(ull& d, ull a, ull b) {
    asm("fma.rn.f32x2 %0, %1, %2, %0;" : "+l"(d) : "l"(a), "l"(b));
}
__device__ __forceinline__ ull mul2(ull a, ull b) {
    ull r; asm("mul.rn.f32x2 %0, %1, %2;" : "=l"(r) : "l"(a), "l"(b)); return r;
}
__device__ __forceinline__ float2 u2f(ull v) {
    float2 r; asm("mov.b64 {%0,%1}, %2;" : "=f"(r.x), "=f"(r.y) : "l"(v)); return r;
}
__device__ __forceinline__ ull f2u(float a, float b) {
    ull r; asm("mov.b64 %0, {%1,%2};" : "=l"(r) : "f"(a), "f"(b)); return r;
}
__device__ __forceinline__ float ex2(float x) {
    float r; asm("ex2.approx.ftz.f32 %0, %1;" : "=f"(r) : "f"(x)); return r;
}

// ================= 8-batch GEMV core: halves write partials (no zero needed) ============
__device__ __forceinline__ void gemv_core(const float* __restrict__ W,
                                          const float* __restrict__ bias,
                                          float* __restrict__ Y,
                                          const float* __restrict__ X,
                                          float* xs, int r, int C,
                                          int ystride, int halfsel, bool use_atomic,
                                          int tid, int lane) {
    int Ch = C >> 1;
    int Ch4 = Ch >> 2;
    const float4* Wr = (const float4*)(W + (size_t)r * C + (size_t)halfsel * Ch);
    int nk = Ch4 >> 5;

    float4 wv[8];
    #pragma unroll
    for (int k = 0; k < 8; k++) if (k < nk) wv[k] = Wr[lane + 32 * k];

    int c0 = halfsel * Ch;
    for (int i = tid; i < 8 * Ch4; i += 256) {
        int b = i / Ch4, j = i - b * Ch4;
        ((float4*)xs)[i] = *((const float4*)(X + (size_t)b * C + c0) + j);
    }
    __syncthreads();

    ull a0[B_], a1[B_];
    #pragma unroll
    for (int b = 0; b < B_; b++) { a0[b] = 0ull; a1[b] = 0ull; }

    const ulonglong2* xs2 = (const ulonglong2*)xs;
    #pragma unroll
    for (int k = 0; k < 8; k++) {
        if (k < nk) {
            ull w01 = f2u(wv[k].x, wv[k].y), w23 = f2u(wv[k].z, wv[k].w);
            int base = 32 * k + lane;
            #pragma unroll
            for (int b = 0; b < B_; b++) {
                ulonglong2 xv = xs2[b * Ch4 + base];
                fma2(a0[b], w01, xv.x);
                fma2(a1[b], w23, xv.y);
            }
        }
    }
    float bs = (halfsel == 0) ? bias[r] : 0.f;
    #pragma unroll
    for (int b = 0; b < B_; b++) {
        float2 p = u2f(a0[b]), q = u2f(a1[b]);
        float v = (p.x + p.y) + (q.x + q.y);
        #pragma unroll
        for (int off = 16; off; off >>= 1) v += __shfl_xor_sync(0xffffffffu, v, off);
        if (lane == 0) {
            if (use_atomic) atomicAdd(&Y[(size_t)b * ystride + r], v + bs);
            else            Y[(size_t)b * ystride + r] = v + bs;
        }
    }
}

// wqb gemv: halves -> g_q / g_q2
__global__ void __launch_bounds__(256) gemvqb_kernel(const float* __restrict__ W,
                                                     const float* __restrict__ bias,
                                                     const float* __restrict__ X_unused) {
    __shared__ __align__(16) float xs[8 * 1024];
    int tid = threadIdx.x, w = tid >> 5, lane = tid & 31;
    float* Y = blockIdx.y ? g_q2 : g_q;
    gemv_core(W, bias, Y, g_qa, xs, blockIdx.x * 8 + w, QLR_, 3072, blockIdx.y, false, tid, lane);
}

// wo gemv: atomic into pre-zeroed out
__global__ void __launch_bounds__(256) gemvwo_kernel(const float* __restrict__ W,
                                                     const float* __restrict__ bias,
                                                     float* __restrict__ out) {
    __shared__ __align__(16) float xs[8 * 1024];
    int tid = threadIdx.x, w = tid >> 5, lane = tid & 31;
    gemv_core(W, bias, out, g_ctxv, xs, blockIdx.x * 8 + w, DIM_, DIM_, blockIdx.y, true, tid, lane);
}

// fused wq_a + wkv_a: halves -> (g_qraw|g_qraw2) / (g_kvpe|g_kvpe2)
__global__ void __launch_bounds__(256) gemva_kernel(const float* __restrict__ wqa,
                                                    const float* __restrict__ wqab,
                                                    const float* __restrict__ wkva,
                                                    const float* __restrict__ wkvab,
                                                    const float* __restrict__ X) {
    __shared__ __align__(16) float xs[8 * 1024];
    int tid = threadIdx.x, w = tid >> 5, lane = tid & 31;
    int r = blockIdx.x * 8 + w;
    if (r < QLR_) {
        float* Y = blockIdx.y ? g_qraw2 : g_qraw;
        gemv_core(wqa, wqab, Y, X, xs, r, DIM_, QLR_, blockIdx.y, false, tid, lane);
    } else {
        float* Y = blockIdx.y ? g_kvpe2 : g_kvpe;
        gemv_core(wkva, wkvab, Y, X, xs, r - QLR_, DIM_, 576, blockIdx.y, false, tid, lane);
    }
}

// ================= prep: rms(q_a) and rms(kv)+k_pe rope (reads half-sums) =================
__device__ __forceinline__ float block_sum(float v, float* red) {
    int w = threadIdx.x >> 5, lane = threadIdx.x & 31;
    #pragma unroll
    for (int off = 16; off; off >>= 1) v += __shfl_xor_sync(0xffffffffu, v, off);
    if (lane == 0) red[w] = v;
    __syncthreads();
    if (threadIdx.x < 32) {
        float t = (threadIdx.x < 8) ? red[threadIdx.x] : 0.f;
        #pragma unroll
        for (int off = 4; off; off >>= 1) t += __shfl_xor_sync(0xffffffffu, t, off);
        if (threadIdx.x == 0) red[0] = t;
    }
    __syncthreads();
    return red[0];
}

__global__ void __launch_bounds__(256) prep_kernel(const float* __restrict__ qnw,
                                                   const float* __restrict__ kvnw,
                                                   const float* __restrict__ fcos,
                                                   const float* __restrict__ fsin) {
    __shared__ float red[8];
    int tid = threadIdx.x;
    if (blockIdx.x < B_) {
        int b = blockIdx.x;
        const float* x0 = g_qraw + b * QLR_;
        const float* x1 = g_qraw2 + b * QLR_;
        float ss = 0.f;
        for (int i = tid; i < QLR_; i += 256) { float v = x0[i] + x1[i]; ss += v * v; }
        float tot = block_sum(ss, red);
        float sc = rsqrtf(tot / QLR_ + EPS_);
        for (int i = tid; i < QLR_; i += 256)
            g_qa[b * QLR_ + i] = (x0[i] + x1[i]) * qnw[i] * sc;
    } else {
        int b = blockIdx.x - B_;
        const float* k0 = g_kvpe + b * 576;
        const float* k1 = g_kvpe2 + b * 576;
        float ss = 0.f;
        for (int i = tid; i < KVLR_; i += 256) { float v = k0[i] + k1[i]; ss += v * v; }
        float tot = block_sum(ss, red);
        float sc = rsqrtf(tot / KVLR_ + EPS_);
        for (int i = tid; i < KVLR_; i += 256)
            g_kvnew[b * KVLR_ + i] = (k0[i] + k1[i]) * kvnw[i] * sc;
        if (tid < 32) {
            int j = tid;
            float xr_ = k0[KVLR_ + 2 * j] + k1[KVLR_ + 2 * j];
            float xi  = k0[KVLR_ + 2 * j + 1] + k1[KVLR_ + 2 * j + 1];
            float c = fcos[j], s = fsin[j];
            g_kpenew[b * DR_ + 2 * j]     = xr_ * c - xi * s;
            g_kpenew[b * DR_ + 2 * j + 1] = xr_ * s + xi * c;
        }
    }
}

// ================= qprep v2: one (head, batch) per CTA, 512 threads, MLP-8 ========
// grid (H_, B_) = 128 CTAs. Thread = one output column c in [0,512).
// W_uk rows L2-resident across the 8 batch-blocks of a head.
__global__ void __launch_bounds__(512) qprep_kernel(const float* __restrict__ wkvb,
                                                    const float* __restrict__ fcos,
                                                    const float* __restrict__ fsin) {
    __shared__ float qn[DN_];
    int h = blockIdx.x, b = blockIdx.y, tid = threadIdx.x;
    const float* q0 = g_q  + b * 3072 + h * (DN_ + DR_);
    const float* q1 = g_q2 + b * 3072 + h * (DN_ + DR_);
    if (tid < DN_) {
        qn[tid] = q0[tid] + q1[tid];
    } else if (tid < DN_ + 32) {
        int j = tid - DN_;
        float xr = q0[DN_ + 2 * j] + q1[DN_ + 2 * j];
        float xi = q0[DN_ + 2 * j + 1] + q1[DN_ + 2 * j + 1];
        float c = fcos[j], s = fsin[j];
        g_qpe[(b * H_ + h) * DR_ + 2 * j]     = xr * c - xi * s;
        g_qpe[(b * H_ + h) * DR_ + 2 * j + 1] = xr * s + xi * c;
    }
    __syncthreads();
    const float* Wc = wkvb + (size_t)h * 256 * KVLR_ + tid;
    float acc0 = 0.f, acc1 = 0.f;
    #pragma unroll 8
    for (int d = 0; d < DN_; d += 2) {
        acc0 = fmaf(qn[d],     Wc[(size_t)d * KVLR_],            acc0);
        acc1 = fmaf(qn[d + 1], Wc[(size_t)(d + 1) * KVLR_],      acc1);
    }
    g_qabs[(size_t)(b * H_ + h) * KVLR_ + tid] = acc0 + acc1;
}

// ================= flash-decode attention: R11 winner + 4-chain QK ========
__global__ void __launch_bounds__(128, 2) attn_kernel(const float* __restrict__ kvpre,
                                                      const float* __restrict__ pepre) {
    __shared__ __align__(16) float4 tile[2][TTOK][144];
    int b = blockIdx.y, split = blockIdx.x;
    int t0 = split * CHUNK;
    int t1 = min(t0 + CHUNK, TTOT);
    int tid = threadIdx.x, w = tid >> 5, lane = tid & 31;
    int hl = lane >> 3, s = lane & 7;
    int head = w * 4 + hl;

    ulonglong2 q[18];
    {
        const ulonglong2* qa = (const ulonglong2*)(g_qabs + (size_t)(b * H_ + head) * KVLR_);
        #pragma unroll
        for (int i = 0; i < 16; i++) q[i] = qa[s + 8 * i];
        const ulonglong2* qp = (const ulonglong2*)(g_qpe + (size_t)(b * H_ + head) * DR_);
        q[16] = qp[s];
        q[17] = qp[s + 8];
    }
    ull acc[32];
    #pragma unroll
    for (int i = 0; i < 32; i++) acc[i] = 0ull;
    float m = -INFINITY, l = 0.f;

    const float4* kv4  = (const float4*)kvpre;
    const float4* pe4  = (const float4*)pepre;
    const float4* kvn4 = (const float4*)g_kvnew;
    const float4* pen4 = (const float4*)g_kpenew;

    int ntiles = (t1 - t0 + TTOK - 1) / TTOK;

    auto issue_tile = [&](int buf, int ti) {
        int tb = t0 + ti * TTOK;
        int cnt = min(TTOK, t1 - tb);
        for (int idx = tid; idx < cnt * 144; idx += 128) {
            int tk = idx / 144, j = idx - tk * 144;
            int t = tb + tk;
            const float4* src;
            if (j < 128)
                src = (t < STARTP) ? (kv4 + ((size_t)b * STARTP + t) * 128 + j)
                                   : (kvn4 + b * 128 + j);
            else
                src = (t < STARTP) ? (pe4 + ((size_t)b * STARTP + t) * 16 + (j - 128))
                                   : (pen4 + b * 16 + (j - 128));
            unsigned sa = (unsigned)__cvta_generic_to_shared(&tile[buf][tk][j]);
            asm volatile("cp.async.cg.shared.global [%0], [%1], 16;\n" :: "r"(sa), "l"(src));
        }
        asm volatile("cp.async.commit_group;\n");
    };

    issue_tile(0, 0);
    for (int ti = 0; ti < ntiles; ti++) {
        if (ti + 1 < ntiles) {
            issue_tile((ti + 1) & 1, ti + 1);
            asm volatile("cp.async.wait_group 1;\n");
        } else {
            asm volatile("cp.async.wait_group 0;\n");
        }
        __syncthreads();
        int tb = t0 + ti * TTOK;
        int cnt = min(TTOK, t1 - tb);
        const float4 (*tl)[144] = tile[ti & 1];
        for (int tk = 0; tk < cnt; tk++) {
            const ulonglong2* row = (const ulonglong2*)tl[tk];
            ulonglong2 kr[18];
            #pragma unroll
            for (int i = 0; i < 16; i++) kr[i] = row[s + 8 * i];
            kr[16] = row[128 + s];
            kr[17] = row[128 + s + 8];
            ull a0 = 0ull, a1 = 0ull, a2 = 0ull, a3 = 0ull;
            #pragma unroll
            for (int i = 0; i < 9; i++) {
                fma2(a0, q[i].x, kr[i].x);
                fma2(a1, q[i].y, kr[i].y);
                fma2(a2, q[i + 9].x, kr[i + 9].x);
                fma2(a3, q[i + 9].y, kr[i + 9].y);
            }
            float2 f0 = u2f(a0), f1 = u2f(a1), f2 = u2f(a2), f3 = u2f(a3);
            float sc = ((f0.x + f0.y) + (f1.x + f1.y)) + ((f2.x + f2.y) + (f3.x + f3.y));
            sc += __shfl_xor_sync(0xffffffffu, sc, 1);
            sc += __shfl_xor_sync(0xffffffffu, sc, 2);
            sc += __shfl_xor_sync(0xffffffffu, sc, 4);
            sc *= SCL2E_;
            if (sc > m) {
                float corr = ex2(m - sc);
                m = sc;
                l *= corr;
                ull c2 = f2u(corr, corr);
                #pragma unroll
                for (int i = 0; i < 32; i++) acc[i] = mul2(acc[i], c2);
            }
            float p = ex2(sc - m);
            l += p;
            ull p2 = f2u(p, p);
            #pragma unroll
            for (int i = 0; i < 16; i++) {
                fma2(acc[2 * i],     p2, kr[i].x);
                fma2(acc[2 * i + 1], p2, kr[i].y);
            }
        }
        __syncthreads();
    }
    float4* dst = (float4*)(g_pout + ((size_t)(b * NSPLIT + split) * H_ + head) * KVLR_);
    #pragma unroll
    for (int i = 0; i < 16; i++) {
        float2 lo = u2f(acc[2 * i]), hi = u2f(acc[2 * i + 1]);
        dst[s + 8 * i] = make_float4(lo.x, lo.y, hi.x, hi.y);
    }
    if (s == 0) {
        float* ml = g_pml + ((b * NSPLIT + split) * H_ + head) * 2;
        ml[0] = m;     // log2 domain
        ml[1] = l;
    }
}

// ================= postcomb: combine + W_uv projection + zero out slice =================
__global__ void __launch_bounds__(256) postcomb_kernel(const float* __restrict__ wkvb,
                                                       float* __restrict__ out) {
    __shared__ float msm[NSPLIT], lsm[NSPLIT], esm[NSPLIT];
    __shared__ float invL;
    __shared__ __align__(16) float cs[KVLR_];
    int h = blockIdx.x, b = blockIdx.y, tid = threadIdx.x;
    int w = tid >> 5, lane = tid & 31;

    if (tid < DV_) out[b * DIM_ + h * DV_ + tid] = 0.f;

    if (tid < NSPLIT) {
        const float* ml = g_pml + ((b * NSPLIT + tid) * H_ + h) * 2;
        msm[tid] = ml[0];
        lsm[tid] = ml[1];
    }
    __syncthreads();
    if (tid == 0) {
        float M = -INFINITY;
        for (int sp = 0; sp < NSPLIT; sp++) M = fmaxf(M, msm[sp]);
        float L = 0.f;
        for (int sp = 0; sp < NSPLIT; sp++) {
            float e = ex2(msm[sp] - M);
            esm[sp] = e;
            L += e * lsm[sp];
        }
        invL = 1.0f / L;
    }
    __syncthreads();
    float a0 = 0.f, a1 = 0.f;
    #pragma unroll 4
    for (int sp = 0; sp < NSPLIT; sp++) {
        float e = esm[sp];
        const float* pp = g_pout + ((size_t)(b * NSPLIT + sp) * H_ + h) * KVLR_;
        a0 += e * pp[tid];
        a1 += e * pp[tid + 256];
    }
    float iv = invL;
    cs[tid]       = a0 * iv;
    cs[tid + 256] = a1 * iv;
    __syncthreads();

    const ulonglong2* cs2 = (const ulonglong2*)cs;
    #pragma unroll
    for (int k = 0; k < 16; k++) {
        int d = w * 16 + k;
        const ulonglong2* wr = (const ulonglong2*)(wkvb + (size_t)(h * 256 + DN_ + d) * KVLR_);
        ull a0u = 0ull, a1u = 0ull;
        #pragma unroll
        for (int j = lane; j < 128; j += 32) {
            ulonglong2 wv = __ldg(wr + j);
            ulonglong2 xv = cs2[j];
            fma2(a0u, wv.x, xv.x);
            fma2(a1u, wv.y, xv.y);
        }
        float2 f0 = u2f(a0u), f1 = u2f(a1u);
        float a = (f0.x + f0.y) + (f1.x + f1.y);
        #pragma unroll
        for (int off = 16; off; off >>= 1) a += __shfl_xor_sync(0xffffffffu, a, off);
        if (lane == 0) g_ctxv[b * DIM_ + h * DV_ + d] = a;
    }
}

// ---------------- launch ----------------
extern "C" void kernel_launch(void* const* d_in, const int* in_sizes, int n_in,
                              void* d_out, int out_size) {
    const float* x     = (const float*)d_in[0];
    const float* fcos  = (const float*)d_in[2];
    const float* fsin  = (const float*)d_in[3];
    const float* kvpre = (const float*)d_in[4];
    const float* pepre = (const float*)d_in[5];
    const float* wqa   = (const float*)d_in[6];
    const float* wqab  = (const float*)d_in[7];
    const float* qnw   = (const float*)d_in[8];
    const float* wqb   = (const float*)d_in[9];
    const float* wqbb  = (const float*)d_in[10];
    const float* wkva  = (const float*)d_in[11];
    const float* wkvab = (const float*)d_in[12];
    const float* kvnw  = (const float*)d_in[13];
    const float* wkvb  = (const float*)d_in[14];
    const float* wo    = (const float*)d_in[15];
    const float* wob   = (const float*)d_in[16];
    float* out = (float*)d_out;

    gemva_kernel<<<dim3((QLR_ + 576) / 8, 2), 256>>>(wqa, wqab, wkva, wkvab, x);
    prep_kernel<<<16, 256>>>(qnw, kvnw, fcos, fsin);
    gemvqb_kernel<<<dim3(3072 / 8, 2), 256>>>(wqb, wqbb, nullptr);
    qprep_kernel<<<dim3(H_, B_), 512>>>(wkvb, fcos, fsin);
    attn_kernel<<<dim3(NSPLIT, B_), 128>>>(kvpre, pepre);
    postcomb_kernel<<<dim3(H_, B_), 256>>>(wkvb, out);
    gemvwo_kernel<<<dim3(DIM_ / 8, 2), 256>>>(wo, wob, out);
}